// round 2
// baseline (speedup 1.0000x reference)
#include <cuda_runtime.h>
#include <math.h>

#define N 8192
#define F 128
#define MAXNZ 1024

// Scratch (device globals — no allocation allowed in kernel_launch)
__device__ float g_xp[(size_t)N * F];   // x' = xW + b
__device__ float g_f1[N];
__device__ float g_f2[N];

// ---------------------------------------------------------------------------
// Kernel A: x' = x @ W + bias, fused f1/f2 = x' . phi in the epilogue.
// Block = 32 rows x 128 cols, 256 threads, 4x4 register tile per thread.
// Each warp owns 4 complete rows -> shuffle-reduce for the phi projections.
// ---------------------------------------------------------------------------
__global__ void __launch_bounds__(256) xw_kernel(const float* __restrict__ x,
                                                 const float* __restrict__ W,
                                                 const float* __restrict__ bias,
                                                 const float* __restrict__ phi) {
    __shared__ float Ws[64][128];      // 32 KB k-tile of W
    __shared__ float xsT[64][36];      // transposed x tile [k][row], padded

    const int tid  = threadIdx.x;
    const int row0 = blockIdx.x * 32;
    const int col0 = (tid & 31) * 4;   // 32 col-threads * 4 cols
    const int rloc = (tid >> 5) * 4;   // 8 warps * 4 rows

    float acc[4][4];
    #pragma unroll
    for (int r = 0; r < 4; r++)
        #pragma unroll
        for (int c = 0; c < 4; c++) acc[r][c] = bias[col0 + c];

    #pragma unroll
    for (int kt = 0; kt < 128; kt += 64) {
        for (int idx = tid; idx < 64 * 128; idx += 256) {
            int k = idx >> 7, c = idx & 127;
            Ws[k][c] = W[(kt + k) * 128 + c];
        }
        for (int idx = tid; idx < 32 * 64; idx += 256) {
            int r = idx >> 6, k = idx & 63;
            xsT[k][r] = x[(size_t)(row0 + r) * 128 + kt + k];
        }
        __syncthreads();

        #pragma unroll 8
        for (int k = 0; k < 64; k++) {
            float4 xv = *reinterpret_cast<const float4*>(&xsT[k][rloc]);
            float4 wv = *reinterpret_cast<const float4*>(&Ws[k][col0]);
            float xr[4] = {xv.x, xv.y, xv.z, xv.w};
            float wc[4] = {wv.x, wv.y, wv.z, wv.w};
            #pragma unroll
            for (int r = 0; r < 4; r++)
                #pragma unroll
                for (int c = 0; c < 4; c++)
                    acc[r][c] += xr[r] * wc[c];
        }
        __syncthreads();
    }

    // Store x' and compute per-row phi projections (warp-level).
    float4 p1 = *reinterpret_cast<const float4*>(&phi[col0]);
    float4 p2 = *reinterpret_cast<const float4*>(&phi[128 + col0]);
    #pragma unroll
    for (int r = 0; r < 4; r++) {
        float4 o = make_float4(acc[r][0], acc[r][1], acc[r][2], acc[r][3]);
        *reinterpret_cast<float4*>(&g_xp[(size_t)(row0 + rloc + r) * 128 + col0]) = o;

        float a1 = o.x * p1.x + o.y * p1.y + o.z * p1.z + o.w * p1.w;
        float a2 = o.x * p2.x + o.y * p2.y + o.z * p2.z + o.w * p2.w;
        #pragma unroll
        for (int off = 16; off; off >>= 1) {
            a1 += __shfl_xor_sync(0xffffffffu, a1, off);
            a2 += __shfl_xor_sync(0xffffffffu, a2, off);
        }
        if ((tid & 31) == 0) {
            g_f1[row0 + rloc + r] = a1;
            g_f2[row0 + rloc + r] = a2;
        }
    }
}

// ---------------------------------------------------------------------------
// Kernel C: per-row sparse softmax-attention.
// One CTA per row i: stream adj row, compact nonzeros (adj!=0 || j==i) into
// smem buffer with leaky-relu scores, exact softmax (max-sub), then gather-
// accumulate h_i over ~82 neighbors (x' rows live in L2).
// ---------------------------------------------------------------------------
__global__ void __launch_bounds__(256) gat_attn_kernel(const float* __restrict__ adj,
                                                       float* __restrict__ out) {
    const int i = blockIdx.x;
    __shared__ int   s_idx[MAXNZ];
    __shared__ float s_val[MAXNZ];
    __shared__ int   s_cnt;
    __shared__ float s_red[8];
    __shared__ float s_bcast;
    __shared__ float s_acc[128];

    const int tid = threadIdx.x;
    if (tid == 0) s_cnt = 0;
    __syncthreads();

    const float f1i = g_f1[i];
    const float4* arow = reinterpret_cast<const float4*>(adj + (size_t)i * N);

    #pragma unroll 4
    for (int t = tid; t < N / 4; t += 256) {
        float4 a = arow[t];
        float av[4] = {a.x, a.y, a.z, a.w};
        int jb = t * 4;
        #pragma unroll
        for (int c = 0; c < 4; c++) {
            int j = jb + c;
            if (av[c] != 0.f || j == i) {
                float s = f1i + g_f2[j];
                s = (s > 0.f) ? s : 0.2f * s;   // leaky_relu(0.2)
                int p = atomicAdd(&s_cnt, 1);
                if (p < MAXNZ) { s_idx[p] = j; s_val[p] = s; }
            }
        }
    }
    __syncthreads();
    const int cnt = min(s_cnt, MAXNZ);

    // ---- block max ----
    float m = -INFINITY;
    for (int k = tid; k < cnt; k += 256) m = fmaxf(m, s_val[k]);
    #pragma unroll
    for (int o = 16; o; o >>= 1) m = fmaxf(m, __shfl_xor_sync(0xffffffffu, m, o));
    if ((tid & 31) == 0) s_red[tid >> 5] = m;
    __syncthreads();
    if (tid == 0) {
        float mm = s_red[0];
        #pragma unroll
        for (int w = 1; w < 8; w++) mm = fmaxf(mm, s_red[w]);
        s_bcast = mm;
    }
    __syncthreads();
    const float mx = s_bcast;

    // ---- exp + sum ----
    float sum = 0.f;
    for (int k = tid; k < cnt; k += 256) {
        float e = __expf(s_val[k] - mx);
        s_val[k] = e;
        sum += e;
    }
    #pragma unroll
    for (int o = 16; o; o >>= 1) sum += __shfl_xor_sync(0xffffffffu, sum, o);
    if ((tid & 31) == 0) s_red[tid >> 5] = sum;
    __syncthreads();
    if (tid == 0) {
        float ss = 0.f;
        #pragma unroll
        for (int w = 0; w < 8; w++) ss += s_red[w];
        s_bcast = 1.f / ss;
    }
    __syncthreads();
    const float inv = s_bcast;

    // ---- gather-accumulate: 128 cols, 2-way split over neighbors ----
    const int col  = tid & 127;
    const int part = tid >> 7;
    float acc = 0.f;
    for (int k = part; k < cnt; k += 2)
        acc += s_val[k] * g_xp[(size_t)s_idx[k] * 128 + col];

    if (part == 0) s_acc[col] = acc;
    __syncthreads();
    if (part == 1)
        out[(size_t)i * 128 + col] = (s_acc[col] + acc) * inv;
}

// ---------------------------------------------------------------------------
extern "C" void kernel_launch(void* const* d_in, const int* in_sizes, int n_in,
                              void* d_out, int out_size) {
    const float* adj  = (const float*)d_in[0];
    const float* x    = (const float*)d_in[1];
    const float* W    = (const float*)d_in[2];
    const float* bias = (const float*)d_in[3];
    const float* phi  = (const float*)d_in[4];
    float* out = (float*)d_out;

    xw_kernel<<<N / 32, 256>>>(x, W, bias, phi);
    gat_attn_kernel<<<N, 256>>>(adj, out);
}